// round 1
// baseline (speedup 1.0000x reference)
#include <cuda_runtime.h>
#include <cstdint>
#include <math.h>

// AntisymmetricRNN: x_{t+1} = x_t + 0.01*tanh(A x_t + by), A = triu(W,1)-triu(W,1)^T - eps*I
// Batch columns independent -> persistent kernel, 1 CTA per 2 batch columns, no grid sync.
// fp32 throughout; packed f32x2 FMA (FFMA2) for full 128 FMA/cyc/SM rate on sm_103a.

constexpr int   Nn      = 256;
constexpr int   Tmax    = 1000;
constexpr float STEPF   = 0.01f;
constexpr float EPSF    = 0.001f;
constexpr int   THREADS = 512;     // 256 rows x 2 K-halves
constexpr int   NR      = 40;      // f32-pairs of A per thread held in registers
constexpr int   NS      = 24;      // f32-pairs of A per thread held in smem
// NR + NS = 64 pairs = 128 columns of A per thread (one K-half of one row)

struct SmemLayout {
    ulonglong2 a[NS / 2][THREADS];   // 12 * 512 * 16B = 96 KB, [iter][thread] -> conflict-free
    float      x[2][Nn];             // current state, 2 batch columns
    float      part[2][2][Nn];       // [col][half][row] partial sums
    float      byv[Nn];              // bias
};

__device__ __forceinline__ void fma2(unsigned long long& d,
                                     unsigned long long a,
                                     unsigned long long b) {
    asm("fma.rn.f32x2 %0, %1, %2, %0;" : "+l"(d) : "l"(a), "l"(b));
}
__device__ __forceinline__ unsigned long long pk2(float lo, float hi) {
    unsigned long long v;
    asm("mov.b64 %0, {%1, %2};" : "=l"(v) : "f"(lo), "f"(hi));
    return v;
}
__device__ __forceinline__ float2 upk2(unsigned long long v) {
    float2 r;
    asm("mov.b64 {%0, %1}, %2;" : "=f"(r.x), "=f"(r.y) : "l"(v));
    return r;
}

__device__ __forceinline__ float aval(const float* __restrict__ W, int i, int j) {
    if (j > i) return W[i * Nn + j];
    if (j < i) return -W[j * Nn + i];
    return -EPSF;
}

__global__ void __launch_bounds__(THREADS, 1)
antisym_rnn_kernel(const float* __restrict__ X0,
                   const float* __restrict__ W,
                   const float* __restrict__ by,
                   float* __restrict__ out) {
    extern __shared__ unsigned char smraw[];
    SmemLayout* sm = reinterpret_cast<SmemLayout*>(smraw);

    const int t     = threadIdx.x;
    const int i     = t & (Nn - 1);   // row of A this thread contributes to
    const int h     = t >> 8;         // which K-half (j in [128h, 128h+128))
    const int b0    = blockIdx.x * 2; // two batch columns per CTA
    const int jbase = h * 128;

    // ---- init state + bias ----
    if (h == 0) {
        sm->x[0][i] = X0[(size_t)b0 * Nn + i];
        sm->byv[i]  = by[i];
    } else {
        sm->x[1][i] = X0[(size_t)(b0 + 1) * Nn + i];
    }

    // ---- build this thread's A chunk: 64 packed f32 pairs ----
    unsigned long long areg[NR];
#pragma unroll
    for (int p = 0; p < NR; ++p) {
        const int j = jbase + 2 * p;
        areg[p] = pk2(aval(W, i, j), aval(W, i, j + 1));
    }
#pragma unroll
    for (int q = 0; q < NS / 2; ++q) {
        const int p0 = NR + 2 * q;
        const int j  = jbase + 2 * p0;
        ulonglong2 v;
        v.x = pk2(aval(W, i, j),     aval(W, i, j + 1));
        v.y = pk2(aval(W, i, j + 2), aval(W, i, j + 3));
        sm->a[q][t] = v;
    }
    __syncthreads();

    // ---- t = 0 output (initial state) ----
    out[((size_t)(b0 + h) * Tmax + 0) * Nn + i] = sm->x[h][i];
    float* outp = out + ((size_t)(b0 + h) * Tmax) * Nn + i;

    const float* x0p = &sm->x[0][jbase];
    const float* x1p = &sm->x[1][jbase];

    // ---- time loop (sequential) ----
    for (int s = 1; s < Tmax; ++s) {
        unsigned long long acc0 = 0ULL, acc1 = 0ULL;

        // register-resident A pairs
#pragma unroll
        for (int q = 0; q < NR / 2; ++q) {
            ulonglong2 xa = *reinterpret_cast<const ulonglong2*>(x0p + 4 * q);
            ulonglong2 xb = *reinterpret_cast<const ulonglong2*>(x1p + 4 * q);
            fma2(acc0, areg[2 * q],     xa.x);
            fma2(acc0, areg[2 * q + 1], xa.y);
            fma2(acc1, areg[2 * q],     xb.x);
            fma2(acc1, areg[2 * q + 1], xb.y);
        }
        // smem-resident A pairs
#pragma unroll
        for (int q = 0; q < NS / 2; ++q) {
            ulonglong2 a2 = sm->a[q][t];
            ulonglong2 xa = *reinterpret_cast<const ulonglong2*>(x0p + 2 * NR + 4 * q);
            ulonglong2 xb = *reinterpret_cast<const ulonglong2*>(x1p + 2 * NR + 4 * q);
            fma2(acc0, a2.x, xa.x);
            fma2(acc0, a2.y, xa.y);
            fma2(acc1, a2.x, xb.x);
            fma2(acc1, a2.y, xb.y);
        }

        const float2 r0 = upk2(acc0);
        const float2 r1 = upk2(acc1);
        sm->part[0][h][i] = r0.x + r0.y;
        sm->part[1][h][i] = r1.x + r1.y;
        __syncthreads();

        // finalize: thread (h, i) owns column h, row i
        const float y  = sm->part[h][0][i] + sm->part[h][1][i] + sm->byv[i];
        const float xn = sm->x[h][i] + STEPF * tanhf(y);
        sm->x[h][i] = xn;
        outp[(size_t)s * Nn] = xn;
        __syncthreads();
    }
}

extern "C" void kernel_launch(void* const* d_in, const int* in_sizes, int n_in,
                              void* d_out, int out_size) {
    const float* X0 = (const float*)d_in[0];
    const float* W  = (const float*)d_in[1];
    const float* by = (const float*)d_in[2];
    float* out      = (float*)d_out;

    const int smem_bytes = (int)sizeof(SmemLayout);
    cudaFuncSetAttribute(antisym_rnn_kernel,
                         cudaFuncAttributeMaxDynamicSharedMemorySize, smem_bytes);

    antisym_rnn_kernel<<<128, THREADS, smem_bytes>>>(X0, W, by, out);
}

// round 4
// speedup vs baseline: 1.4335x; 1.4335x over previous
#include <cuda_runtime.h>
#include <cstdint>
#include <math.h>

// AntisymmetricRNN: x_{t+1} = x_t + 0.01*tanh(A x_t + by)
// A = triu(W,1) - triu(W,1)^T - eps*I.  N=256, BS=256, TMAX=1000.
// Persistent kernel: 128 CTAs x 2 batch columns, sequential over time.
// Round 2: per-thread tile 4 rows x 32 cols (was 1x128) to cut smem x-broadcast
// wavefronts 4x; crossbar was the binding resource (L1=78%, fma=28%).

constexpr int   Nn      = 256;
constexpr int   Tmax    = 1000;
constexpr float STEPF   = 0.01f;
constexpr float EPSF    = 0.001f;
constexpr int   THREADS = 512;   // 64 row-groups (4 rows each) x 8 k-chunks (32 cols each)
constexpr int   NSQ     = 12;    // ulonglong2 smem A slots per thread (24 pairs)
// Per thread: 4 rows x 16 pairs = 64 pairs. 40 pairs in regs (10/row), 24 in smem (6/row).

struct SmemLayout {
    ulonglong2 a[NSQ][THREADS];  // 12 * 512 * 16B = 96 KB
    float      x[2][Nn];         // state, 2 batch columns
    float      part[2][8][Nn];   // [col][kc][row] partial sums, 16 KB
    float      byv[Nn];
};

__device__ __forceinline__ void fma2(unsigned long long& d,
                                     unsigned long long a,
                                     unsigned long long b) {
    asm("fma.rn.f32x2 %0, %1, %2, %0;" : "+l"(d) : "l"(a), "l"(b));
}
__device__ __forceinline__ unsigned long long pk2(float lo, float hi) {
    unsigned long long v;
    asm("mov.b64 %0, {%1, %2};" : "=l"(v) : "f"(lo), "f"(hi));
    return v;
}
__device__ __forceinline__ float2 upk2(unsigned long long v) {
    float2 r;
    asm("mov.b64 {%0, %1}, %2;" : "=f"(r.x), "=f"(r.y) : "l"(v));
    return r;
}

__device__ __forceinline__ float aval(const float* __restrict__ W, int i, int j) {
    if (j > i) return W[i * Nn + j];
    if (j < i) return -W[j * Nn + i];
    return -EPSF;
}

__global__ void __launch_bounds__(THREADS, 1)
antisym_rnn_kernel(const float* __restrict__ X0,
                   const float* __restrict__ W,
                   const float* __restrict__ by,
                   float* __restrict__ out) {
    extern __shared__ unsigned char smraw[];
    SmemLayout* sm = reinterpret_cast<SmemLayout*>(smraw);

    const int t  = threadIdx.x;
    const int i5 = t & 63;        // base row; thread owns rows i5 + 64*r, r=0..3
    const int kc = t >> 6;        // k-chunk: cols [32*kc, 32*kc+32)
    const int j0 = kc * 32;
    const int b0 = blockIdx.x * 2;

    // reduce-phase mapping: thread t -> (col, row)
    const int rrow = t & 255;
    const int rcol = t >> 8;

    // ---- init state + bias ----
    sm->x[rcol][rrow] = X0[(size_t)(b0 + rcol) * Nn + rrow];
    if (rcol == 0) sm->byv[rrow] = by[rrow];

    // ---- build A chunk: 4 rows x 16 pairs; 10 pairs/row regs, 6 pairs/row smem ----
    unsigned long long areg[40];
#pragma unroll
    for (int r = 0; r < 4; ++r) {
        const int row = i5 + 64 * r;
#pragma unroll
        for (int p = 0; p < 10; ++p) {
            const int j = j0 + 2 * p;
            areg[r * 10 + p] = pk2(aval(W, row, j), aval(W, row, j + 1));
        }
#pragma unroll
        for (int pi = 5; pi < 8; ++pi) {
            const int j = j0 + 4 * pi;
            ulonglong2 v;
            v.x = pk2(aval(W, row, j),     aval(W, row, j + 1));
            v.y = pk2(aval(W, row, j + 2), aval(W, row, j + 3));
            sm->a[(pi - 5) * 4 + r][t] = v;
        }
    }
    __syncthreads();

    // ---- t = 0 output (initial state) ----
    out[((size_t)(b0 + rcol) * Tmax + 0) * Nn + rrow] = sm->x[rcol][rrow];
    float* outp = out + ((size_t)(b0 + rcol) * Tmax) * Nn + rrow;

    const float* x0p = &sm->x[0][j0];
    const float* x1p = &sm->x[1][j0];

    // ---- sequential time loop ----
    for (int s = 1; s < Tmax; ++s) {
        unsigned long long acc[4][2];
#pragma unroll
        for (int r = 0; r < 4; ++r) { acc[r][0] = 0ULL; acc[r][1] = 0ULL; }

        // register-resident A: pairs 0..9 per row  (pi = 0..4, two pairs per pi)
#pragma unroll
        for (int pi = 0; pi < 5; ++pi) {
            const ulonglong2 xa = *reinterpret_cast<const ulonglong2*>(x0p + 4 * pi);
            const ulonglong2 xb = *reinterpret_cast<const ulonglong2*>(x1p + 4 * pi);
#pragma unroll
            for (int r = 0; r < 4; ++r) {
                fma2(acc[r][0], areg[r * 10 + 2 * pi],     xa.x);
                fma2(acc[r][0], areg[r * 10 + 2 * pi + 1], xa.y);
                fma2(acc[r][1], areg[r * 10 + 2 * pi],     xb.x);
                fma2(acc[r][1], areg[r * 10 + 2 * pi + 1], xb.y);
            }
        }
        // smem-resident A: pairs 10..15 per row  (pi = 5..7)
#pragma unroll
        for (int pi = 5; pi < 8; ++pi) {
            const ulonglong2 xa = *reinterpret_cast<const ulonglong2*>(x0p + 4 * pi);
            const ulonglong2 xb = *reinterpret_cast<const ulonglong2*>(x1p + 4 * pi);
#pragma unroll
            for (int r = 0; r < 4; ++r) {
                const ulonglong2 a2 = sm->a[(pi - 5) * 4 + r][t];
                fma2(acc[r][0], a2.x, xa.x);
                fma2(acc[r][0], a2.y, xa.y);
                fma2(acc[r][1], a2.x, xb.x);
                fma2(acc[r][1], a2.y, xb.y);
            }
        }

        // write 8 partials: part[col][kc][i5 + 64r]
#pragma unroll
        for (int r = 0; r < 4; ++r) {
            const float2 f0 = upk2(acc[r][0]);
            const float2 f1 = upk2(acc[r][1]);
            sm->part[0][kc][i5 + 64 * r] = f0.x + f0.y;
            sm->part[1][kc][i5 + 64 * r] = f1.x + f1.y;
        }
        __syncthreads();

        // reduce: thread (rcol, rrow) sums 8 k-chunk partials
        float y = sm->byv[rrow];
#pragma unroll
        for (int k = 0; k < 8; ++k) y += sm->part[rcol][k][rrow];

        const float xn = sm->x[rcol][rrow] + STEPF * tanhf(y);
        sm->x[rcol][rrow] = xn;
        outp[(size_t)s * Nn] = xn;
        __syncthreads();
    }
}

extern "C" void kernel_launch(void* const* d_in, const int* in_sizes, int n_in,
                              void* d_out, int out_size) {
    const float* X0 = (const float*)d_in[0];
    const float* W  = (const float*)d_in[1];
    const float* by = (const float*)d_in[2];
    float* out      = (float*)d_out;

    const int smem_bytes = (int)sizeof(SmemLayout);
    cudaFuncSetAttribute(antisym_rnn_kernel,
                         cudaFuncAttributeMaxDynamicSharedMemorySize, smem_bytes);

    antisym_rnn_kernel<<<128, THREADS, smem_bytes>>>(X0, W, by, out);
}